// round 7
// baseline (speedup 1.0000x reference)
#include <cuda_runtime.h>
#include <cuda_fp16.h>
#include <math.h>
#include <stdint.h>

#define NB 16
#define NN 1024

// ---------------- helpers ----------------
__device__ __forceinline__ uint32_t smem_to_u32(const void* p) {
    uint32_t a;
    asm("{ .reg .u64 t; cvta.to.shared.u64 t, %1; cvt.u32.u64 %0, t; }" : "=r"(a) : "l"(p));
    return a;
}
__device__ __forceinline__ void cp16(uint32_t dst, const void* src) {
    asm volatile("cp.async.cg.shared.global [%0], [%1], 16;" :: "r"(dst), "l"(src));
}
__device__ __forceinline__ void cp_commit() { asm volatile("cp.async.commit_group;" ::: "memory"); }
__device__ __forceinline__ void cp_wait0()  { asm volatile("cp.async.wait_group 0;" ::: "memory"); }

__device__ __forceinline__ void ldsm4(uint32_t* r, uint32_t addr) {
    asm volatile("ldmatrix.sync.aligned.m8n8.x4.shared.b16 {%0,%1,%2,%3}, [%4];"
                 : "=r"(r[0]), "=r"(r[1]), "=r"(r[2]), "=r"(r[3]) : "r"(addr));
}
__device__ __forceinline__ void mma_fp16(float* c, const uint32_t* a, const uint32_t* b) {
    asm volatile(
        "mma.sync.aligned.m16n8k16.row.col.f32.f16.f16.f32 "
        "{%0,%1,%2,%3}, {%4,%5,%6,%7}, {%8,%9}, {%0,%1,%2,%3};"
        : "+f"(c[0]), "+f"(c[1]), "+f"(c[2]), "+f"(c[3])
        : "r"(a[0]), "r"(a[1]), "r"(a[2]), "r"(a[3]), "r"(b[0]), "r"(b[1]));
}

// ---------------- scratch (device globals) ----------------
#define TOT ((size_t)NB * NN * NN)
__device__ __half g_f1h[TOT], g_f1l[TOT];
__device__ __half g_f2h[TOT], g_f2l[TOT];
__device__ __half g_wth[NN * NN], g_wtl[NN * NN];
__device__ __half g_a1h[TOT], g_a1l[TOT];
__device__ __half g_et[TOT];               // E_T (single fp16 limb)
__device__ __half g_er[TOT];               // E_r (single fp16 limb)
__device__ float g_cc[TOT];
__device__ float g_pmax[NB * 8 * NN];
__device__ float g_psum[NB * 8 * NN];
__device__ float g_mc[NB * NN], g_invc[NB * NN], g_invr[NB * NN];

// ---------------- split-2 fp16 GEMM via mma.sync ----------------
// C[M,N] = A[M,K] · B[N,K]^T.
// A_SPLIT=1: A hi+lo limbs -> 3 products. A_SPLIT=0: single A limb -> 2 products.
// Tile 128x128, BK=32, 512 threads (16 warps: 4m x 4n), warp tile 32x32.
// 1 CTA/SM -> 1024 CTAs / 148 SMs = 6.92 waves (98.8% packing) with the
// dense-tile mma/ldsm ratio of the 128x128 config.
#define BK 32
#define ROWB 80                         // bytes per smem row (64 data + 16 pad)
#define AH_OFF 0
#define AL_OFF (128 * ROWB)             // 10240
#define BH_OFF (2 * 128 * ROWB)         // 20480
#define BL_OFF (BH_OFF + 128 * ROWB)    // 30720
#define SLOTB (BL_OFF + 128 * ROWB)     // 40960
#define SMEM_DYN (2 * SLOTB)            // 81920
#define KT 32

template<bool A_SPLIT, bool SPLIT_OUT, bool SCALE>
__global__ __launch_bounds__(512, 1)
void gemm_kernel(const __half* __restrict__ Ah, const __half* __restrict__ Al,
                 const __half* __restrict__ Bh, const __half* __restrict__ Bl,
                 float* __restrict__ C, __half* __restrict__ Ch, __half* __restrict__ Cl,
                 const float* __restrict__ scaleg, size_t sA, size_t sB, size_t sC)
{
    extern __shared__ char dsm[];
    const uint32_t sb = smem_to_u32(dsm);

    const int tid = threadIdx.x;
    const int lane = tid & 31;
    const int w = tid >> 5;
    const int wm = w & 3;        // 0..3 -> 32 rows each
    const int wn = w >> 2;       // 0..3 -> 32 cols each
    const int b = blockIdx.z;
    const int m0 = blockIdx.y * 128;
    const int n0 = blockIdx.x * 128;

    Ah += (size_t)b * sA; if (A_SPLIT) Al += (size_t)b * sA;
    Bh += (size_t)b * sB; Bl += (size_t)b * sB;

    float acc[2][4][4];
    #pragma unroll
    for (int i = 0; i < 2; i++)
        #pragma unroll
        for (int j = 0; j < 4; j++)
            #pragma unroll
            for (int q = 0; q < 4; q++) acc[i][j][q] = 0.0f;

    // 512 threads: A = 128 rows x 4 chunks (one pass per limb), B same.
    auto load_stage = [&](int slot, int kt) {
        uint32_t base = sb + slot * SLOTB;
        int k0 = kt * BK;
        int row = tid >> 2, ch = tid & 3;
        uint32_t so = row * ROWB + ch * 16;
        size_t gA = ((size_t)(m0 + row) << 10) + k0 + ch * 8;
        size_t gB = ((size_t)(n0 + row) << 10) + k0 + ch * 8;
        cp16(base + AH_OFF + so, Ah + gA);
        if (A_SPLIT) cp16(base + AL_OFF + so, Al + gA);
        cp16(base + BH_OFF + so, Bh + gB);
        cp16(base + BL_OFF + so, Bl + gB);
        cp_commit();
    };

    load_stage(0, 0);

    const int arow = wm * 32 + (lane & 15);                      // + mt*16
    const int achk = lane >> 4;                                  // + 2*ks
    const int brow = wn * 32 + ((lane & 16) >> 1) + (lane & 7);  // + p*16
    const int bchk = (lane >> 3) & 1;                            // + 2*ks

    for (int kt = 0; kt < KT; kt++) {
        cp_wait0();
        __syncthreads();
        if (kt + 1 < KT) load_stage((kt + 1) & 1, kt + 1);

        uint32_t sa = sb + (kt & 1) * SLOTB;
        #pragma unroll
        for (int ks = 0; ks < 2; ks++) {
            uint32_t a_h[2][4], a_l[2][4], b_h[2][4], b_l[2][4];
            #pragma unroll
            for (int mt = 0; mt < 2; mt++) {
                uint32_t ad = sa + AH_OFF + (arow + mt * 16) * ROWB + (ks * 2 + achk) * 16;
                ldsm4(a_h[mt], ad);
                if (A_SPLIT) ldsm4(a_l[mt], ad + (AL_OFF - AH_OFF));
            }
            #pragma unroll
            for (int p = 0; p < 2; p++) {
                uint32_t bd = sa + BH_OFF + (brow + p * 16) * ROWB + (ks * 2 + bchk) * 16;
                ldsm4(b_h[p], bd);
                ldsm4(b_l[p], bd + (BL_OFF - BH_OFF));
            }
            // product-major passes (8 independent accumulators per pass)
            #pragma unroll
            for (int mt = 0; mt < 2; mt++)
                #pragma unroll
                for (int nt = 0; nt < 4; nt++)
                    mma_fp16(acc[mt][nt], a_h[mt], &b_h[nt >> 1][(nt & 1) * 2]);
            #pragma unroll
            for (int mt = 0; mt < 2; mt++)
                #pragma unroll
                for (int nt = 0; nt < 4; nt++)
                    mma_fp16(acc[mt][nt], a_h[mt], &b_l[nt >> 1][(nt & 1) * 2]);
            if (A_SPLIT) {
                #pragma unroll
                for (int mt = 0; mt < 2; mt++)
                    #pragma unroll
                    for (int nt = 0; nt < 4; nt++)
                        mma_fp16(acc[mt][nt], a_l[mt], &b_h[nt >> 1][(nt & 1) * 2]);
            }
        }
    }

    // ---- epilogue: direct global stores ----
    #pragma unroll
    for (int mt = 0; mt < 2; mt++) {
        int mr = m0 + wm * 32 + mt * 16 + (lane >> 2);
        float s0 = 1.0f, s1 = 1.0f;
        if (SCALE) {
            s0 = scaleg[b * NN + mr];
            s1 = scaleg[b * NN + mr + 8];
        }
        #pragma unroll
        for (int nt = 0; nt < 4; nt++) {
            int nc = n0 + wn * 32 + nt * 8 + (lane & 3) * 2;
            size_t i0 = (size_t)b * sC + ((size_t)mr << 10) + nc;
            size_t i1 = i0 + (8 << 10);
            float v00 = acc[mt][nt][0] * s0, v01 = acc[mt][nt][1] * s0;
            float v10 = acc[mt][nt][2] * s1, v11 = acc[mt][nt][3] * s1;
            if (SPLIT_OUT) {
                __half h00 = __float2half_rn(v00), h01 = __float2half_rn(v01);
                __half h10 = __float2half_rn(v10), h11 = __float2half_rn(v11);
                *(__half2*)(Ch + i0) = __halves2half2(h00, h01);
                *(__half2*)(Ch + i1) = __halves2half2(h10, h11);
                *(__half2*)(Cl + i0) = __halves2half2(
                    __float2half_rn(v00 - __half2float(h00)),
                    __float2half_rn(v01 - __half2float(h01)));
                *(__half2*)(Cl + i1) = __halves2half2(
                    __float2half_rn(v10 - __half2float(h10)),
                    __float2half_rn(v11 - __half2float(h11)));
            } else {
                *(float2*)(C + i0) = make_float2(v00, v01);
                *(float2*)(C + i1) = make_float2(v10, v11);
            }
        }
    }
}

// ---------------- elementwise / reduction kernels ----------------
__global__ void split_kernel(const float* __restrict__ x, __half* __restrict__ h,
                             __half* __restrict__ l)
{
    size_t i = ((size_t)blockIdx.x * 256 + threadIdx.x) * 4;
    float4 v = *(const float4*)(x + i);
    union { __half hh[4]; uint2 u; } ph, pl;
    float f[4] = {v.x, v.y, v.z, v.w};
    #pragma unroll
    for (int j = 0; j < 4; j++) {
        __half b = __float2half_rn(f[j]);
        ph.hh[j] = b;
        pl.hh[j] = __float2half_rn(f[j] - __half2float(b));
    }
    *(uint2*)(h + i) = ph.u;
    *(uint2*)(l + i) = pl.u;
}

__global__ void wtrans_kernel(const float* __restrict__ W, __half* __restrict__ h,
                              __half* __restrict__ l)
{
    __shared__ float tile[32][33];
    int e0 = blockIdx.x << 5, d0 = blockIdx.y << 5;
    int tx = threadIdx.x, ty = threadIdx.y;
    #pragma unroll
    for (int j = 0; j < 4; j++) {
        int r = ty + (j << 3);
        tile[r][tx] = W[(size_t)(d0 + r) * NN + e0 + tx];
    }
    __syncthreads();
    #pragma unroll
    for (int j = 0; j < 4; j++) {
        int r = ty + (j << 3);
        float v = tile[tx][r];                      // W[d0+tx][e0+r]
        __half hh = __float2half_rn(v);
        size_t o = (size_t)(e0 + r) * NN + d0 + tx; // WT[e][d]
        h[o] = hh;
        l[o] = __float2half_rn(v - __half2float(hh));
    }
}

__global__ void pmax_kernel(const float* __restrict__ cc, float* __restrict__ pm)
{
    int b = blockIdx.z, sc = blockIdx.y;
    int t = blockIdx.x * 256 + threadIdx.x;
    const float* p = cc + ((size_t)b << 20) + ((size_t)sc << 17) + t;
    float m = -INFINITY;
    #pragma unroll 8
    for (int s = 0; s < 128; s++) m = fmaxf(m, p[(size_t)s << 10]);
    pm[((b << 3) + sc) * NN + t] = m;
}

// fused: col-max reduce (from partials) + partial exp-sum
__global__ void psum_kernel(const float* __restrict__ cc, const float* __restrict__ pm,
                            float* __restrict__ ps, float* __restrict__ mc)
{
    int b = blockIdx.z, sc = blockIdx.y;
    int t = blockIdx.x * 256 + threadIdx.x;
    float m = -INFINITY;
    #pragma unroll
    for (int c = 0; c < 8; c++) m = fmaxf(m, pm[((b << 3) + c) * NN + t]);
    if (sc == 0) mc[b * NN + t] = m;
    const float* p = cc + ((size_t)b << 20) + ((size_t)sc << 17) + t;
    float sum = 0.0f;
    #pragma unroll 4
    for (int s = 0; s < 128; s++) sum += expf(p[(size_t)s << 10] - m);
    ps[((b << 3) + sc) * NN + t] = sum;
}
__global__ void sumred_kernel(const float* __restrict__ ps, float* __restrict__ invc)
{
    int b = blockIdx.y;
    int t = blockIdx.x * 256 + threadIdx.x;
    float s = 0.0f;
    #pragma unroll
    for (int c = 0; c < 8; c++) s += ps[((b << 3) + c) * NN + t];
    invc[b * NN + t] = 1.0f / s;
}

// E_T[t][s] = exp(cc[s][t] - mc[t]) as single fp16 (transposed write)
__global__ void expT_kernel(const float* __restrict__ cc, const float* __restrict__ mc,
                            __half* __restrict__ E)
{
    __shared__ float tile[32][33];
    int b = blockIdx.z;
    int s0 = blockIdx.x << 5, t0 = blockIdx.y << 5;
    int tx = threadIdx.x, ty = threadIdx.y;
    size_t cb = (size_t)b << 20;
    #pragma unroll
    for (int j = 0; j < 4; j++) {
        int r = ty + (j << 3);
        tile[r][tx] = cc[cb + ((size_t)(s0 + r) << 10) + t0 + tx];
    }
    __syncthreads();
    #pragma unroll
    for (int j = 0; j < 4; j++) {
        int r = ty + (j << 3);
        float m = mc[b * NN + t0 + r];
        float e = expf(tile[tx][r] - m);            // cc[s0+tx][t0+r]
        E[cb + ((size_t)(t0 + r) << 10) + s0 + tx] = __float2half_rn(e);
    }
}

// row softmax: E_r (single fp16) + invr
__global__ void exprow_kernel(const float* __restrict__ cc, __half* __restrict__ E,
                              float* __restrict__ invr)
{
    __shared__ float red[256];
    int b = blockIdx.y, s = blockIdx.x;
    size_t base = ((size_t)b << 20) + ((size_t)s << 10);
    int t0 = threadIdx.x * 4;
    float4 q = *(const float4*)(cc + base + t0);
    float m = fmaxf(fmaxf(q.x, q.y), fmaxf(q.z, q.w));
    red[threadIdx.x] = m;
    __syncthreads();
    #pragma unroll
    for (int o = 128; o > 0; o >>= 1) {
        if (threadIdx.x < o) red[threadIdx.x] = fmaxf(red[threadIdx.x], red[threadIdx.x + o]);
        __syncthreads();
    }
    m = red[0];
    __syncthreads();
    float e[4] = {expf(q.x - m), expf(q.y - m), expf(q.z - m), expf(q.w - m)};
    union { __half h[4]; uint2 u; } ph;
    #pragma unroll
    for (int j = 0; j < 4; j++) ph.h[j] = __float2half_rn(e[j]);
    *(uint2*)(E + base + t0) = ph.u;
    red[threadIdx.x] = e[0] + e[1] + e[2] + e[3];
    __syncthreads();
    #pragma unroll
    for (int o = 128; o > 0; o >>= 1) {
        if (threadIdx.x < o) red[threadIdx.x] += red[threadIdx.x + o];
        __syncthreads();
    }
    if (threadIdx.x == 0) invr[b * NN + s] = 1.0f / red[0];
}

// ---------------- host ----------------
extern "C" void kernel_launch(void* const* d_in, const int* in_sizes, int n_in,
                              void* d_out, int out_size)
{
    const float* f1 = (const float*)d_in[0];
    const float* f2 = (const float*)d_in[1];
    const float* W  = (const float*)d_in[2];
    float* out1 = (float*)d_out;
    float* out2 = out1 + ((size_t)NB << 20);

    __half *f1h, *f1l, *f2h, *f2l, *wth, *wtl, *a1h, *a1l, *et, *er;
    float *cc, *pm, *ps, *mc, *invc, *invr;
    cudaGetSymbolAddress((void**)&f1h, g_f1h); cudaGetSymbolAddress((void**)&f1l, g_f1l);
    cudaGetSymbolAddress((void**)&f2h, g_f2h); cudaGetSymbolAddress((void**)&f2l, g_f2l);
    cudaGetSymbolAddress((void**)&wth, g_wth); cudaGetSymbolAddress((void**)&wtl, g_wtl);
    cudaGetSymbolAddress((void**)&a1h, g_a1h); cudaGetSymbolAddress((void**)&a1l, g_a1l);
    cudaGetSymbolAddress((void**)&et, g_et);   cudaGetSymbolAddress((void**)&er, g_er);
    cudaGetSymbolAddress((void**)&cc, g_cc);
    cudaGetSymbolAddress((void**)&pm, g_pmax); cudaGetSymbolAddress((void**)&ps, g_psum);
    cudaGetSymbolAddress((void**)&mc, g_mc);   cudaGetSymbolAddress((void**)&invc, g_invc);
    cudaGetSymbolAddress((void**)&invr, g_invr);

    cudaFuncSetAttribute(gemm_kernel<true,  true,  false>, cudaFuncAttributeMaxDynamicSharedMemorySize, SMEM_DYN);
    cudaFuncSetAttribute(gemm_kernel<true,  false, false>, cudaFuncAttributeMaxDynamicSharedMemorySize, SMEM_DYN);
    cudaFuncSetAttribute(gemm_kernel<false, false, true>,  cudaFuncAttributeMaxDynamicSharedMemorySize, SMEM_DYN);

    const size_t MBe = (size_t)1 << 20;
    dim3 gg(8, 8, NB);   // 128x128 tiles -> 1024 CTAs, 1 CTA/SM -> 6.92 waves

    // fp16 splits
    split_kernel<<<16384, 256>>>(f1, f1h, f1l);
    split_kernel<<<16384, 256>>>(f2, f2h, f2l);
    wtrans_kernel<<<dim3(32, 32), dim3(32, 8)>>>(W, wth, wtl);

    // 1. a1 = f1 @ W  (3-product) -> fp16 split out
    gemm_kernel<true,  true,  false><<<gg, 512, SMEM_DYN>>>(f1h, f1l, wth, wtl,
                                                            nullptr, a1h, a1l, nullptr, MBe, 0, MBe);
    // 2. cc = a1 @ f2^T (3-product) -> fp32
    gemm_kernel<true,  false, false><<<gg, 512, SMEM_DYN>>>(a1h, a1l, f2h, f2l,
                                                            cc, nullptr, nullptr, nullptr, MBe, MBe, MBe);
    // 3. column softmax stats
    pmax_kernel<<<dim3(4, 8, NB), 256>>>(cc, pm);
    psum_kernel<<<dim3(4, 8, NB), 256>>>(cc, pm, ps, mc);
    sumred_kernel<<<dim3(4, NB), 256>>>(ps, invc);
    // 4. E_T (single fp16)
    expT_kernel<<<dim3(32, 32, NB), dim3(32, 8)>>>(cc, mc, et);
    // 5. out1[t,s] = invc[t] * sum_d E_T[t,d] * f1[s,d]  (2-product)
    gemm_kernel<false, false, true><<<gg, 512, SMEM_DYN>>>(et, nullptr, f1h, f1l,
                                                           out1, nullptr, nullptr, invc, MBe, MBe, MBe);
    // 6. row softmax (single fp16 E_r)
    exprow_kernel<<<dim3(NN, NB), 256>>>(cc, er, invr);
    // 7. out2[s,t] = invr[s] * sum_d E_r[s,d] * f2[t,d]  (2-product)
    gemm_kernel<false, false, true><<<gg, 512, SMEM_DYN>>>(er, nullptr, f2h, f2l,
                                                           out2, nullptr, nullptr, invr, MBe, MBe, MBe);
}

// round 8
// speedup vs baseline: 1.1245x; 1.1245x over previous
#include <cuda_runtime.h>
#include <cuda_fp16.h>
#include <math.h>
#include <stdint.h>

#define NB 16
#define NN 1024

// ---------------- helpers ----------------
__device__ __forceinline__ uint32_t smem_to_u32(const void* p) {
    uint32_t a;
    asm("{ .reg .u64 t; cvta.to.shared.u64 t, %1; cvt.u32.u64 %0, t; }" : "=r"(a) : "l"(p));
    return a;
}
__device__ __forceinline__ void cp16(uint32_t dst, const void* src) {
    asm volatile("cp.async.cg.shared.global [%0], [%1], 16;" :: "r"(dst), "l"(src));
}
__device__ __forceinline__ void cp_commit() { asm volatile("cp.async.commit_group;" ::: "memory"); }
__device__ __forceinline__ void cp_wait0()  { asm volatile("cp.async.wait_group 0;" ::: "memory"); }

__device__ __forceinline__ void ldsm4(uint32_t* r, uint32_t addr) {
    asm volatile("ldmatrix.sync.aligned.m8n8.x4.shared.b16 {%0,%1,%2,%3}, [%4];"
                 : "=r"(r[0]), "=r"(r[1]), "=r"(r[2]), "=r"(r[3]) : "r"(addr));
}
__device__ __forceinline__ void mma_fp16(float* c, const uint32_t* a, const uint32_t* b) {
    asm volatile(
        "mma.sync.aligned.m16n8k16.row.col.f32.f16.f16.f32 "
        "{%0,%1,%2,%3}, {%4,%5,%6,%7}, {%8,%9}, {%0,%1,%2,%3};"
        : "+f"(c[0]), "+f"(c[1]), "+f"(c[2]), "+f"(c[3])
        : "r"(a[0]), "r"(a[1]), "r"(a[2]), "r"(a[3]), "r"(b[0]), "r"(b[1]));
}

// ---------------- scratch (device globals) ----------------
#define TOT ((size_t)NB * NN * NN)
__device__ __half g_f1h[TOT], g_f1l[TOT];
__device__ __half g_f2h[TOT], g_f2l[TOT];
__device__ __half g_wth[NN * NN], g_wtl[NN * NN];
__device__ __half g_a1h[TOT], g_a1l[TOT];
__device__ __half g_et[TOT];               // E_T (single fp16)
__device__ __half g_er[TOT];               // E_r (single fp16)
__device__ float g_cc[TOT];
__device__ float g_pmax[NB * 8 * NN];
__device__ float g_psum[NB * 8 * NN];
__device__ float g_mc[NB * NN], g_invc[NB * NN], g_invr[NB * NN];

// ---------------- fp16 GEMM body (R4 layout: warp tile 64x32, density 4) ----------------
// C[M,N] = A[M,K] · B[N,K]^T. A_SPLIT: 3 products (hh,hl,lh); else 2 (hh,hl).
// 256 threads, 8 warps (2m x 4n), 128x128 tile, BK=32, 2-stage, 2 CTA/SM.
#define BK 32
#define ROWB 80                         // bytes per smem row (64 data + 16 pad)
#define AH_OFF 0
#define AL_OFF (128 * ROWB)             // 10240
#define BH_OFF (2 * 128 * ROWB)         // 20480
#define BL_OFF (3 * 128 * ROWB)         // 30720
#define SLOTB (4 * 128 * ROWB)          // 40960
#define SMEM_DYN (2 * SLOTB)            // 81920 -> 2 CTAs/SM
#define KT 32

template<bool A_SPLIT, bool SPLIT_OUT, bool SCALE>
__device__ __forceinline__ void gemm_body(
    const __half* __restrict__ Ah, const __half* __restrict__ Al,
    const __half* __restrict__ Bh, const __half* __restrict__ Bl,
    float* __restrict__ C, __half* __restrict__ Ch, __half* __restrict__ Cl,
    const float* __restrict__ scb, char* dsm)
{
    const uint32_t sb = smem_to_u32(dsm);
    const int tid = threadIdx.x;
    const int lane = tid & 31;
    const int w = tid >> 5;
    const int wm = w & 1;        // 2 m groups of 64 rows
    const int wn = w >> 1;       // 4 n groups of 32 cols
    const int m0 = blockIdx.y * 128;
    const int n0 = blockIdx.x * 128;

    float acc[4][4][4];
    #pragma unroll
    for (int i = 0; i < 4; i++)
        #pragma unroll
        for (int j = 0; j < 4; j++)
            #pragma unroll
            for (int q = 0; q < 4; q++) acc[i][j][q] = 0.0f;

    auto load_stage = [&](int slot, int kt) {
        uint32_t base = sb + slot * SLOTB;
        int k0 = kt * BK;
        #pragma unroll
        for (int i = 0; i < 2; i++) {
            int f = tid + i * 256;
            int row = f >> 2, ch = f & 3;
            uint32_t so = row * ROWB + ch * 16;
            size_t gA = ((size_t)(m0 + row) << 10) + k0 + ch * 8;
            size_t gB = ((size_t)(n0 + row) << 10) + k0 + ch * 8;
            cp16(base + AH_OFF + so, Ah + gA);
            if (A_SPLIT) cp16(base + AL_OFF + so, Al + gA);
            cp16(base + BH_OFF + so, Bh + gB);
            cp16(base + BL_OFF + so, Bl + gB);
        }
        cp_commit();
    };

    load_stage(0, 0);

    const int arow = wm * 64 + (lane & 15);                      // + mt*16
    const int achk = lane >> 4;                                  // + 2*ks
    const int brow = wn * 32 + ((lane & 16) >> 1) + (lane & 7);  // + p*16
    const int bchk = (lane >> 3) & 1;                            // + 2*ks

    for (int kt = 0; kt < KT; kt++) {
        cp_wait0();
        __syncthreads();
        if (kt + 1 < KT) load_stage((kt + 1) & 1, kt + 1);

        uint32_t sa = sb + (kt & 1) * SLOTB;
        #pragma unroll
        for (int ks = 0; ks < 2; ks++) {
            uint32_t a_h[4][4], a_l[4][4], b_h[2][4], b_l[2][4];
            #pragma unroll
            for (int mt = 0; mt < 4; mt++) {
                uint32_t ad = sa + AH_OFF + (arow + mt * 16) * ROWB + (ks * 2 + achk) * 16;
                ldsm4(a_h[mt], ad);
                if (A_SPLIT) ldsm4(a_l[mt], ad + (AL_OFF - AH_OFF));
            }
            #pragma unroll
            for (int p = 0; p < 2; p++) {
                uint32_t bd = sa + BH_OFF + (brow + p * 16) * ROWB + (ks * 2 + bchk) * 16;
                ldsm4(b_h[p], bd);
                ldsm4(b_l[p], bd + (BL_OFF - BH_OFF));
            }
            // product-major passes: 16 independent accumulators per pass
            #pragma unroll
            for (int mt = 0; mt < 4; mt++)
                #pragma unroll
                for (int nt = 0; nt < 4; nt++)
                    mma_fp16(acc[mt][nt], a_h[mt], &b_h[nt >> 1][(nt & 1) * 2]);
            #pragma unroll
            for (int mt = 0; mt < 4; mt++)
                #pragma unroll
                for (int nt = 0; nt < 4; nt++)
                    mma_fp16(acc[mt][nt], a_h[mt], &b_l[nt >> 1][(nt & 1) * 2]);
            if (A_SPLIT) {
                #pragma unroll
                for (int mt = 0; mt < 4; mt++)
                    #pragma unroll
                    for (int nt = 0; nt < 4; nt++)
                        mma_fp16(acc[mt][nt], a_l[mt], &b_h[nt >> 1][(nt & 1) * 2]);
            }
        }
    }

    // ---- epilogue ----
    #pragma unroll
    for (int mt = 0; mt < 4; mt++) {
        int mr = m0 + wm * 64 + mt * 16 + (lane >> 2);
        float s0 = 1.0f, s1 = 1.0f;
        if (SCALE) {
            s0 = scb[mr];
            s1 = scb[mr + 8];
        }
        #pragma unroll
        for (int nt = 0; nt < 4; nt++) {
            int nc = n0 + wn * 32 + nt * 8 + (lane & 3) * 2;
            size_t i0 = ((size_t)mr << 10) + nc;
            size_t i1 = i0 + (8 << 10);
            float v00 = acc[mt][nt][0] * s0, v01 = acc[mt][nt][1] * s0;
            float v10 = acc[mt][nt][2] * s1, v11 = acc[mt][nt][3] * s1;
            if (SPLIT_OUT) {
                __half h00 = __float2half_rn(v00), h01 = __float2half_rn(v01);
                __half h10 = __float2half_rn(v10), h11 = __float2half_rn(v11);
                *(__half2*)(Ch + i0) = __halves2half2(h00, h01);
                *(__half2*)(Ch + i1) = __halves2half2(h10, h11);
                *(__half2*)(Cl + i0) = __halves2half2(
                    __float2half_rn(v00 - __half2float(h00)),
                    __float2half_rn(v01 - __half2float(h01)));
                *(__half2*)(Cl + i1) = __halves2half2(
                    __float2half_rn(v10 - __half2float(h10)),
                    __float2half_rn(v11 - __half2float(h11)));
            } else {
                *(float2*)(C + i0) = make_float2(v00, v01);
                *(float2*)(C + i1) = make_float2(v10, v11);
            }
        }
    }
}

template<bool A_SPLIT, bool SPLIT_OUT, bool SCALE>
__global__ __launch_bounds__(256, 2)
void gemm_kernel(const __half* __restrict__ Ah, const __half* __restrict__ Al,
                 const __half* __restrict__ Bh, const __half* __restrict__ Bl,
                 float* __restrict__ C, __half* __restrict__ Ch, __half* __restrict__ Cl,
                 const float* __restrict__ scaleg, size_t sA, size_t sB, size_t sC)
{
    extern __shared__ char dsm[];
    const size_t b = blockIdx.z;
    gemm_body<A_SPLIT, SPLIT_OUT, SCALE>(
        Ah + b * sA, A_SPLIT ? Al + b * sA : nullptr,
        Bh + b * sB, Bl + b * sB,
        SPLIT_OUT ? nullptr : C + b * sC,
        SPLIT_OUT ? Ch + b * sC : nullptr,
        SPLIT_OUT ? Cl + b * sC : nullptr,
        SCALE ? scaleg + b * NN : nullptr, dsm);
}

// fused attention GEMMs: z<16 -> out1 = diag(invc)·E_T·f1^T ; z>=16 -> out2 = diag(invr)·E_r·f2^T
__global__ __launch_bounds__(256, 2)
void gemm34_kernel(const __half* __restrict__ A3, const __half* __restrict__ B3h,
                   const __half* __restrict__ B3l, const float* __restrict__ sc3,
                   float* __restrict__ C3,
                   const __half* __restrict__ A4, const __half* __restrict__ B4h,
                   const __half* __restrict__ B4l, const float* __restrict__ sc4,
                   float* __restrict__ C4)
{
    extern __shared__ char dsm[];
    const int z = blockIdx.z;
    const size_t off = (size_t)(z & 15) << 20;
    const int bn = (z & 15) * NN;
    if (z < 16)
        gemm_body<false, false, true>(A3 + off, nullptr, B3h + off, B3l + off,
                                      C3 + off, nullptr, nullptr, sc3 + bn, dsm);
    else
        gemm_body<false, false, true>(A4 + off, nullptr, B4h + off, B4l + off,
                                      C4 + off, nullptr, nullptr, sc4 + bn, dsm);
}

// ---------------- elementwise / reduction kernels ----------------
__global__ void split_kernel(const float* __restrict__ x, __half* __restrict__ h,
                             __half* __restrict__ l)
{
    size_t i = ((size_t)blockIdx.x * 256 + threadIdx.x) * 4;
    float4 v = *(const float4*)(x + i);
    union { __half hh[4]; uint2 u; } ph, pl;
    float f[4] = {v.x, v.y, v.z, v.w};
    #pragma unroll
    for (int j = 0; j < 4; j++) {
        __half b = __float2half_rn(f[j]);
        ph.hh[j] = b;
        pl.hh[j] = __float2half_rn(f[j] - __half2float(b));
    }
    *(uint2*)(h + i) = ph.u;
    *(uint2*)(l + i) = pl.u;
}

__global__ void wtrans_kernel(const float* __restrict__ W, __half* __restrict__ h,
                              __half* __restrict__ l)
{
    __shared__ float tile[32][33];
    int e0 = blockIdx.x << 5, d0 = blockIdx.y << 5;
    int tx = threadIdx.x, ty = threadIdx.y;
    #pragma unroll
    for (int j = 0; j < 4; j++) {
        int r = ty + (j << 3);
        tile[r][tx] = W[(size_t)(d0 + r) * NN + e0 + tx];
    }
    __syncthreads();
    #pragma unroll
    for (int j = 0; j < 4; j++) {
        int r = ty + (j << 3);
        float v = tile[tx][r];                      // W[d0+tx][e0+r]
        __half hh = __float2half_rn(v);
        size_t o = (size_t)(e0 + r) * NN + d0 + tx; // WT[e][d]
        h[o] = hh;
        l[o] = __float2half_rn(v - __half2float(hh));
    }
}

__global__ void pmax_kernel(const float* __restrict__ cc, float* __restrict__ pm)
{
    int b = blockIdx.z, sc = blockIdx.y;
    int t = blockIdx.x * 256 + threadIdx.x;
    const float* p = cc + ((size_t)b << 20) + ((size_t)sc << 17) + t;
    float m = -INFINITY;
    #pragma unroll 8
    for (int s = 0; s < 128; s++) m = fmaxf(m, p[(size_t)s << 10]);
    pm[((b << 3) + sc) * NN + t] = m;
}

__global__ void psum_kernel(const float* __restrict__ cc, const float* __restrict__ pm,
                            float* __restrict__ ps, float* __restrict__ mc)
{
    int b = blockIdx.z, sc = blockIdx.y;
    int t = blockIdx.x * 256 + threadIdx.x;
    float m = -INFINITY;
    #pragma unroll
    for (int c = 0; c < 8; c++) m = fmaxf(m, pm[((b << 3) + c) * NN + t]);
    if (sc == 0) mc[b * NN + t] = m;
    const float* p = cc + ((size_t)b << 20) + ((size_t)sc << 17) + t;
    float sum = 0.0f;
    #pragma unroll 4
    for (int s = 0; s < 128; s++) sum += expf(p[(size_t)s << 10] - m);
    ps[((b << 3) + sc) * NN + t] = sum;
}
__global__ void sumred_kernel(const float* __restrict__ ps, float* __restrict__ invc)
{
    int b = blockIdx.y;
    int t = blockIdx.x * 256 + threadIdx.x;
    float s = 0.0f;
    #pragma unroll
    for (int c = 0; c < 8; c++) s += ps[((b << 3) + c) * NN + t];
    invc[b * NN + t] = 1.0f / s;
}

// E_T[t][s] = exp(cc[s][t] - mc[t]) as fp16 (transposed write)
__global__ void expT_kernel(const float* __restrict__ cc, const float* __restrict__ mc,
                            __half* __restrict__ E)
{
    __shared__ float tile[32][33];
    int b = blockIdx.z;
    int s0 = blockIdx.x << 5, t0 = blockIdx.y << 5;
    int tx = threadIdx.x, ty = threadIdx.y;
    size_t cb = (size_t)b << 20;
    #pragma unroll
    for (int j = 0; j < 4; j++) {
        int r = ty + (j << 3);
        tile[r][tx] = cc[cb + ((size_t)(s0 + r) << 10) + t0 + tx];
    }
    __syncthreads();
    #pragma unroll
    for (int j = 0; j < 4; j++) {
        int r = ty + (j << 3);
        float m = mc[b * NN + t0 + r];
        float e = expf(tile[tx][r] - m);
        E[cb + ((size_t)(t0 + r) << 10) + s0 + tx] = __float2half_rn(e);
    }
}

// row softmax: E_r (fp16) + invr
__global__ void exprow_kernel(const float* __restrict__ cc, __half* __restrict__ E,
                              float* __restrict__ invr)
{
    __shared__ float red[256];
    int b = blockIdx.y, s = blockIdx.x;
    size_t base = ((size_t)b << 20) + ((size_t)s << 10);
    int t0 = threadIdx.x * 4;
    float4 q = *(const float4*)(cc + base + t0);
    float m = fmaxf(fmaxf(q.x, q.y), fmaxf(q.z, q.w));
    red[threadIdx.x] = m;
    __syncthreads();
    #pragma unroll
    for (int o = 128; o > 0; o >>= 1) {
        if (threadIdx.x < o) red[threadIdx.x] = fmaxf(red[threadIdx.x], red[threadIdx.x + o]);
        __syncthreads();
    }
    m = red[0];
    __syncthreads();
    float e[4] = {expf(q.x - m), expf(q.y - m), expf(q.z - m), expf(q.w - m)};
    union { __half h[4]; uint2 u; } ph;
    #pragma unroll
    for (int j = 0; j < 4; j++) ph.h[j] = __float2half_rn(e[j]);
    *(uint2*)(E + base + t0) = ph.u;
    red[threadIdx.x] = e[0] + e[1] + e[2] + e[3];
    __syncthreads();
    #pragma unroll
    for (int o = 128; o > 0; o >>= 1) {
        if (threadIdx.x < o) red[threadIdx.x] += red[threadIdx.x + o];
        __syncthreads();
    }
    if (threadIdx.x == 0) invr[b * NN + s] = 1.0f / red[0];
}

// ---------------- host ----------------
extern "C" void kernel_launch(void* const* d_in, const int* in_sizes, int n_in,
                              void* d_out, int out_size)
{
    const float* f1 = (const float*)d_in[0];
    const float* f2 = (const float*)d_in[1];
    const float* W  = (const float*)d_in[2];
    float* out1 = (float*)d_out;
    float* out2 = out1 + ((size_t)NB << 20);

    __half *f1h, *f1l, *f2h, *f2l, *wth, *wtl, *a1h, *a1l, *et, *er;
    float *cc, *pm, *ps, *mc, *invc, *invr;
    cudaGetSymbolAddress((void**)&f1h, g_f1h); cudaGetSymbolAddress((void**)&f1l, g_f1l);
    cudaGetSymbolAddress((void**)&f2h, g_f2h); cudaGetSymbolAddress((void**)&f2l, g_f2l);
    cudaGetSymbolAddress((void**)&wth, g_wth); cudaGetSymbolAddress((void**)&wtl, g_wtl);
    cudaGetSymbolAddress((void**)&a1h, g_a1h); cudaGetSymbolAddress((void**)&a1l, g_a1l);
    cudaGetSymbolAddress((void**)&et, g_et);   cudaGetSymbolAddress((void**)&er, g_er);
    cudaGetSymbolAddress((void**)&cc, g_cc);
    cudaGetSymbolAddress((void**)&pm, g_pmax); cudaGetSymbolAddress((void**)&ps, g_psum);
    cudaGetSymbolAddress((void**)&mc, g_mc);   cudaGetSymbolAddress((void**)&invc, g_invc);
    cudaGetSymbolAddress((void**)&invr, g_invr);

    cudaFuncSetAttribute(gemm_kernel<true, true,  false>, cudaFuncAttributeMaxDynamicSharedMemorySize, SMEM_DYN);
    cudaFuncSetAttribute(gemm_kernel<true, false, false>, cudaFuncAttributeMaxDynamicSharedMemorySize, SMEM_DYN);
    cudaFuncSetAttribute(gemm34_kernel, cudaFuncAttributeMaxDynamicSharedMemorySize, SMEM_DYN);

    const size_t MBe = (size_t)1 << 20;
    dim3 gg(8, 8, NB);       // 128x128 tiles -> 1024 CTAs
    dim3 gg34(8, 8, 2 * NB); // fused attention GEMMs -> 2048 CTAs

    // fp16 splits
    split_kernel<<<16384, 256>>>(f1, f1h, f1l);
    split_kernel<<<16384, 256>>>(f2, f2h, f2l);
    wtrans_kernel<<<dim3(32, 32), dim3(32, 8)>>>(W, wth, wtl);

    // 1. a1 = f1 @ W (3-product) -> fp16 split
    gemm_kernel<true, true,  false><<<gg, 256, SMEM_DYN>>>(f1h, f1l, wth, wtl,
                                                           nullptr, a1h, a1l, nullptr, MBe, 0, MBe);
    // 2. cc = a1 @ f2^T (3-product) -> fp32
    gemm_kernel<true, false, false><<<gg, 256, SMEM_DYN>>>(a1h, a1l, f2h, f2l,
                                                           cc, nullptr, nullptr, nullptr, MBe, MBe, MBe);
    // 3. column softmax stats
    pmax_kernel<<<dim3(4, 8, NB), 256>>>(cc, pm);
    psum_kernel<<<dim3(4, 8, NB), 256>>>(cc, pm, ps, mc);
    sumred_kernel<<<dim3(4, NB), 256>>>(ps, invc);
    // 4. E_T (fp16, transposed)
    expT_kernel<<<dim3(32, 32, NB), dim3(32, 8)>>>(cc, mc, et);
    // 5. row softmax (fp16 E_r + invr)
    exprow_kernel<<<dim3(NN, NB), 256>>>(cc, er, invr);
    // 6. fused attention GEMMs (2-product each):
    //    out1[t,s] = invc[t]·Σ_d E_T[t,d]·f1[s,d] ; out2[s,t] = invr[s]·Σ_d E_r[s,d]·f2[t,d]
    gemm34_kernel<<<gg34, 256, SMEM_DYN>>>(et, f1h, f1l, invc, out1,
                                           er, f2h, f2l, invr, out2);
}